// round 1
// baseline (speedup 1.0000x reference)
#include <cuda_runtime.h>
#include <cuda_fp16.h>

#define N_BATCH 4
#define NHEADS  16
#define SEQL    2048
#define HD      64
#define NH      (N_BATCH*NHEADS)   // 64
#define ROWS_ALL (NH*SEQL)         // 131072
#define EMB     1024

// -------- scratch (static device globals; no allocations allowed) --------
__device__ __align__(256) __half  g_q[ROWS_ALL*HD];
__device__ __align__(256) __half  g_k[ROWS_ALL*HD];
__device__ __align__(256) __half  g_v[ROWS_ALL*HD];
__device__ __align__(256) __half  g_att[ROWS_ALL*HD];
__device__ __align__(256) __half  g_wo[EMB*EMB];
__device__ __align__(256) unsigned g_mp[N_BATCH*SEQL*(SEQL/32)];

// -------- helpers --------
__device__ __forceinline__ unsigned smem_u32(const void* p) {
    return (unsigned)__cvta_generic_to_shared(p);
}
__device__ __forceinline__ void ldsm4(unsigned r[4], unsigned addr) {
    asm volatile("ldmatrix.sync.aligned.m8n8.x4.shared.b16 {%0,%1,%2,%3}, [%4];"
        : "=r"(r[0]), "=r"(r[1]), "=r"(r[2]), "=r"(r[3]) : "r"(addr));
}
__device__ __forceinline__ void ldsm4t(unsigned r[4], unsigned addr) {
    asm volatile("ldmatrix.sync.aligned.m8n8.x4.trans.shared.b16 {%0,%1,%2,%3}, [%4];"
        : "=r"(r[0]), "=r"(r[1]), "=r"(r[2]), "=r"(r[3]) : "r"(addr));
}
__device__ __forceinline__ void mma16816(float c[4], const unsigned a[4],
                                         unsigned b0, unsigned b1) {
    asm volatile(
        "mma.sync.aligned.m16n8k16.row.col.f32.f16.f16.f32 "
        "{%0,%1,%2,%3},{%4,%5,%6,%7},{%8,%9},{%0,%1,%2,%3};"
        : "+f"(c[0]), "+f"(c[1]), "+f"(c[2]), "+f"(c[3])
        : "r"(a[0]), "r"(a[1]), "r"(a[2]), "r"(a[3]), "r"(b0), "r"(b1));
}
__device__ __forceinline__ float ex2f(float x) {
    float y; asm("ex2.approx.ftz.f32 %0, %1;" : "=f"(y) : "f"(x)); return y;
}
__device__ __forceinline__ unsigned packh2(float a, float b) {
    __half2 h = __floats2half2_rn(a, b);
    return *reinterpret_cast<unsigned*>(&h);
}

// -------- kernel 1: bitpack the mask (67MB int32 -> 2MB bits) --------
__global__ void pack_mask_kernel(const int* __restrict__ mask) {
    int lane = threadIdx.x & 31;
    int gw   = (blockIdx.x * blockDim.x + threadIdx.x) >> 5;
    int nw   = (gridDim.x * blockDim.x) >> 5;
    const int NW = N_BATCH * SEQL * (SEQL / 32);
    for (int w = gw; w < NW; w += nw) {
        int v = mask[w * 32 + lane];
        unsigned bits = __ballot_sync(0xffffffffu, v != 0);
        if (lane == 0) g_mp[w] = bits;
    }
}

// -------- kernel 2: Wo fp32 -> fp16 --------
__global__ void cvt_wo_kernel(const float* __restrict__ Wo) {
    int i = blockIdx.x * blockDim.x + threadIdx.x;
    int stride = gridDim.x * blockDim.x;
    for (int j = i; j < EMB * EMB / 4; j += stride) {
        float4 f = *(const float4*)&Wo[j * 4];
        *(__half2*)&g_wo[j * 4]     = __floats2half2_rn(f.x, f.y);
        *(__half2*)&g_wo[j * 4 + 2] = __floats2half2_rn(f.z, f.w);
    }
}

// -------- kernel 3: fused QKV projection  (X[131072,64] @ W^T[64,64]) --------
__global__ __launch_bounds__(128) void proj_kernel(
    const float* __restrict__ keys, const float* __restrict__ values,
    const float* __restrict__ queries, const float* __restrict__ Wk,
    const float* __restrict__ Wv, const float* __restrict__ Wq)
{
    __shared__ __half Xs[64 * 72];
    __shared__ __half Ws[64 * 72];
    int which = blockIdx.y;
    const float* X = which == 0 ? keys : (which == 1 ? values : queries);
    const float* W = which == 0 ? Wk   : (which == 1 ? Wv     : Wq);
    __half* out    = which == 0 ? g_k  : (which == 1 ? g_v    : g_q);
    int rowbase = blockIdx.x * 64;
    int tid = threadIdx.x, lane = tid & 31, w = tid >> 5;

    for (int i = tid; i < 1024; i += 128) {
        int r = i >> 4, c4 = (i & 15) * 4;
        float4 f = *(const float4*)&X[(rowbase + r) * 64 + c4];
        *(__half2*)&Xs[r * 72 + c4]     = __floats2half2_rn(f.x, f.y);
        *(__half2*)&Xs[r * 72 + c4 + 2] = __floats2half2_rn(f.z, f.w);
        float4 g = *(const float4*)&W[r * 64 + c4];
        *(__half2*)&Ws[r * 72 + c4]     = __floats2half2_rn(g.x, g.y);
        *(__half2*)&Ws[r * 72 + c4 + 2] = __floats2half2_rn(g.z, g.w);
    }
    __syncthreads();
    int m0 = w * 16;
    float O[8][4];
#pragma unroll
    for (int t = 0; t < 8; t++)
#pragma unroll
        for (int j = 0; j < 4; j++) O[t][j] = 0.f;

#pragma unroll
    for (int kk = 0; kk < 4; kk++) {
        unsigned a[4];
        {
            int row = m0 + (lane & 7) + ((lane >> 3) & 1) * 8;
            int col = kk * 16 + (lane >> 4) * 8;
            ldsm4(a, smem_u32(&Xs[row * 72 + col]));
        }
#pragma unroll
        for (int tp = 0; tp < 4; tp++) {
            unsigned b[4];
            int row = tp * 16 + (lane & 7) + (lane >> 4) * 8;
            int col = kk * 16 + ((lane >> 3) & 1) * 8;
            ldsm4(b, smem_u32(&Ws[row * 72 + col]));
            mma16816(O[2 * tp],     a, b[0], b[1]);
            mma16816(O[2 * tp + 1], a, b[2], b[3]);
        }
    }
    int r0 = lane >> 2, c0l = (lane & 3) * 2;
#pragma unroll
    for (int t = 0; t < 8; t++) {
        int col = t * 8 + c0l;
        *(__half2*)&out[(rowbase + m0 + r0) * 64 + col] =
            __floats2half2_rn(O[t][0], O[t][1]);
        *(__half2*)&out[(rowbase + m0 + r0 + 8) * 64 + col] =
            __floats2half2_rn(O[t][2], O[t][3]);
    }
}

// -------- kernel 4: flash attention, BQ=64 per block, 4 warps --------
__global__ __launch_bounds__(128) void attn_kernel()
{
    __shared__ __half Qs[64 * 72];
    __shared__ __half Ks[64 * 72];
    __shared__ __half Vs[64 * 72];
    __shared__ unsigned Ms[128];

    int qt = blockIdx.x;   // 0..31 query tiles
    int nh = blockIdx.y;   // 0..63 (n*16+h)
    int n  = nh >> 4;
    int tid = threadIdx.x, lane = tid & 31, w = tid >> 5;
    const __half* Qg = g_q + (nh * SEQL + qt * 64) * HD;
    const __half* Kg = g_k + nh * SEQL * HD;
    const __half* Vg = g_v + nh * SEQL * HD;
    const unsigned* Mg = g_mp + (n * SEQL + qt * 64) * (SEQL / 32);

    for (int i = tid; i < 512; i += 128) {
        int r = i >> 3, c8 = (i & 7) * 8;
        *(uint4*)&Qs[r * 72 + c8] = *(const uint4*)&Qg[r * 64 + c8];
    }
    __syncthreads();
    int m0 = w * 16;
    unsigned qa[4][4];
#pragma unroll
    for (int kk = 0; kk < 4; kk++) {
        int row = m0 + (lane & 7) + ((lane >> 3) & 1) * 8;
        int col = kk * 16 + (lane >> 4) * 8;
        ldsm4(qa[kk], smem_u32(&Qs[row * 72 + col]));
    }
    float O[8][4];
#pragma unroll
    for (int t = 0; t < 8; t++)
#pragma unroll
        for (int j = 0; j < 4; j++) O[t][j] = 0.f;
    float mrow0 = -1e30f, mrow1 = -1e30f, lrow0 = 0.f, lrow1 = 0.f;
    const float SC = 0.0450842200278f;  // log2(e)/sqrt(1024)

    for (int kv = 0; kv < SEQL; kv += 64) {
        __syncthreads();
        for (int i = tid; i < 512; i += 128) {
            int r = i >> 3, c8 = (i & 7) * 8;
            *(uint4*)&Ks[r * 72 + c8] = *(const uint4*)&Kg[(kv + r) * 64 + c8];
            *(uint4*)&Vs[r * 72 + c8] = *(const uint4*)&Vg[(kv + r) * 64 + c8];
        }
        Ms[tid] = Mg[(tid >> 1) * (SEQL / 32) + (kv >> 5) + (tid & 1)];
        __syncthreads();

        // S = Q K^T   (fp32 accum)
        float S[8][4];
#pragma unroll
        for (int t = 0; t < 8; t++)
#pragma unroll
            for (int j = 0; j < 4; j++) S[t][j] = 0.f;
#pragma unroll
        for (int kk = 0; kk < 4; kk++) {
#pragma unroll
            for (int tp = 0; tp < 4; tp++) {
                unsigned b[4];
                int row = tp * 16 + (lane & 7) + (lane >> 4) * 8;
                int col = kk * 16 + ((lane >> 3) & 1) * 8;
                ldsm4(b, smem_u32(&Ks[row * 72 + col]));
                mma16816(S[2 * tp],     qa[kk], b[0], b[1]);
                mma16816(S[2 * tp + 1], qa[kk], b[2], b[3]);
            }
        }
        // mask + scale (base-2), online softmax
        int r0 = lane >> 2, c0l = (lane & 3) * 2;
        float rmax0 = -1e30f, rmax1 = -1e30f;
#pragma unroll
        for (int t = 0; t < 8; t++) {
            int col = t * 8 + c0l;
            unsigned w0 = Ms[(m0 + r0) * 2 + (col >> 5)];
            unsigned w1 = Ms[(m0 + r0 + 8) * 2 + (col >> 5)];
            S[t][0] = ((w0 >> (col & 31)) & 1)       ? S[t][0] * SC : -1e30f;
            S[t][1] = ((w0 >> ((col + 1) & 31)) & 1) ? S[t][1] * SC : -1e30f;
            S[t][2] = ((w1 >> (col & 31)) & 1)       ? S[t][2] * SC : -1e30f;
            S[t][3] = ((w1 >> ((col + 1) & 31)) & 1) ? S[t][3] * SC : -1e30f;
            rmax0 = fmaxf(rmax0, fmaxf(S[t][0], S[t][1]));
            rmax1 = fmaxf(rmax1, fmaxf(S[t][2], S[t][3]));
        }
        rmax0 = fmaxf(rmax0, __shfl_xor_sync(0xffffffffu, rmax0, 1));
        rmax0 = fmaxf(rmax0, __shfl_xor_sync(0xffffffffu, rmax0, 2));
        rmax1 = fmaxf(rmax1, __shfl_xor_sync(0xffffffffu, rmax1, 1));
        rmax1 = fmaxf(rmax1, __shfl_xor_sync(0xffffffffu, rmax1, 2));
        float mn0 = fmaxf(mrow0, rmax0), mn1 = fmaxf(mrow1, rmax1);
        float a0 = ex2f(mrow0 - mn0), a1 = ex2f(mrow1 - mn1);
        mrow0 = mn0; mrow1 = mn1;

        unsigned P[8][2];
        float rs0 = 0.f, rs1 = 0.f;
#pragma unroll
        for (int t = 0; t < 8; t++) {
            float p0 = ex2f(S[t][0] - mn0), p1 = ex2f(S[t][1] - mn0);
            float p2 = ex2f(S[t][2] - mn1), p3 = ex2f(S[t][3] - mn1);
            rs0 += p0 + p1; rs1 += p2 + p3;
            P[t][0] = packh2(p0, p1);
            P[t][1] = packh2(p2, p3);
            O[t][0] *= a0; O[t][1] *= a0; O[t][2] *= a1; O[t][3] *= a1;
        }
        rs0 += __shfl_xor_sync(0xffffffffu, rs0, 1);
        rs0 += __shfl_xor_sync(0xffffffffu, rs0, 2);
        rs1 += __shfl_xor_sync(0xffffffffu, rs1, 1);
        rs1 += __shfl_xor_sync(0xffffffffu, rs1, 2);
        lrow0 = lrow0 * a0 + rs0;
        lrow1 = lrow1 * a1 + rs1;

        // O += P @ V  (V via ldmatrix.trans)
#pragma unroll
        for (int kk = 0; kk < 4; kk++) {
            unsigned pa[4] = {P[2 * kk][0], P[2 * kk][1],
                              P[2 * kk + 1][0], P[2 * kk + 1][1]};
#pragma unroll
            for (int tp = 0; tp < 4; tp++) {
                unsigned b[4];
                int row = kk * 16 + (lane & 7) + ((lane >> 3) & 1) * 8;
                int col = tp * 16 + (lane >> 4) * 8;
                ldsm4t(b, smem_u32(&Vs[row * 72 + col]));
                mma16816(O[2 * tp],     pa, b[0], b[1]);
                mma16816(O[2 * tp + 1], pa, b[2], b[3]);
            }
        }
    }
    float inv0 = 1.f / lrow0, inv1 = 1.f / lrow1;
    __half* outp = g_att + (nh * SEQL + qt * 64) * HD;
    int r0 = lane >> 2, c0l = (lane & 3) * 2;
#pragma unroll
    for (int t = 0; t < 8; t++) {
        int col = t * 8 + c0l;
        *(__half2*)&outp[(m0 + r0) * 64 + col] =
            __floats2half2_rn(O[t][0] * inv0, O[t][1] * inv0);
        *(__half2*)&outp[(m0 + r0 + 8) * 64 + col] =
            __floats2half2_rn(O[t][2] * inv1, O[t][3] * inv1);
    }
}

// -------- kernel 5: output projection  out = X[8192,1024] @ Wo^T + bo --------
__global__ __launch_bounds__(128) void outproj_kernel(
    float* __restrict__ out, const float* __restrict__ bo)
{
    __shared__ __half Xs[64 * 72];
    __shared__ __half Ws[64 * 72];
    __shared__ float  Bs[64];
    int mt = blockIdx.x, nt = blockIdx.y;
    int tid = threadIdx.x, lane = tid & 31, w = tid >> 5;
    if (tid < 64) Bs[tid] = bo[nt * 64 + tid];

    float O[8][4];
#pragma unroll
    for (int t = 0; t < 8; t++)
#pragma unroll
        for (int j = 0; j < 4; j++) O[t][j] = 0.f;

    int m0 = w * 16;
    for (int ks = 0; ks < 16; ks++) {
        __syncthreads();
        for (int i = tid; i < 512; i += 128) {
            int r = i >> 3, c8 = (i & 7) * 8;
            *(uint4*)&Xs[r * 72 + c8] =
                *(const uint4*)&g_att[(mt * 64 + r) * 1024 + ks * 64 + c8];
            *(uint4*)&Ws[r * 72 + c8] =
                *(const uint4*)&g_wo[(nt * 64 + r) * 1024 + ks * 64 + c8];
        }
        __syncthreads();
#pragma unroll
        for (int kk = 0; kk < 4; kk++) {
            unsigned a[4];
            {
                int row = m0 + (lane & 7) + ((lane >> 3) & 1) * 8;
                int col = kk * 16 + (lane >> 4) * 8;
                ldsm4(a, smem_u32(&Xs[row * 72 + col]));
            }
#pragma unroll
            for (int tp = 0; tp < 4; tp++) {
                unsigned b[4];
                int row = tp * 16 + (lane & 7) + (lane >> 4) * 8;
                int col = kk * 16 + ((lane >> 3) & 1) * 8;
                ldsm4(b, smem_u32(&Ws[row * 72 + col]));
                mma16816(O[2 * tp],     a, b[0], b[1]);
                mma16816(O[2 * tp + 1], a, b[2], b[3]);
            }
        }
    }
    int r0 = lane >> 2, c0l = (lane & 3) * 2;
#pragma unroll
    for (int t = 0; t < 8; t++) {
        int col = t * 8 + c0l;
        float2 v0 = make_float2(O[t][0] + Bs[col], O[t][1] + Bs[col + 1]);
        float2 v1 = make_float2(O[t][2] + Bs[col], O[t][3] + Bs[col + 1]);
        *(float2*)&out[(mt * 64 + m0 + r0) * 1024 + nt * 64 + col] = v0;
        *(float2*)&out[(mt * 64 + m0 + r0 + 8) * 1024 + nt * 64 + col] = v1;
    }
}

// -------- launch --------
extern "C" void kernel_launch(void* const* d_in, const int* in_sizes, int n_in,
                              void* d_out, int out_size)
{
    const float* keys    = (const float*)d_in[0];
    const float* values  = (const float*)d_in[1];
    const float* queries = (const float*)d_in[2];
    const int*   mask    = (const int*)d_in[3];
    const float* Wk      = (const float*)d_in[4];
    const float* Wv      = (const float*)d_in[5];
    const float* Wq      = (const float*)d_in[6];
    const float* Wo      = (const float*)d_in[7];
    const float* bo      = (const float*)d_in[8];
    float* out = (float*)d_out;

    pack_mask_kernel<<<512, 256>>>(mask);
    cvt_wo_kernel<<<256, 256>>>(Wo);
    proj_kernel<<<dim3(ROWS_ALL / 64, 3), 128>>>(keys, values, queries, Wk, Wv, Wq);
    attn_kernel<<<dim3(SEQL / 64, NH), 128>>>();
    outproj_kernel<<<dim3(ROWS_ALL * HD / EMB / 64, EMB / 64), 128>>>(out, bo);
}

// round 2
// speedup vs baseline: 1.6577x; 1.6577x over previous
#include <cuda_runtime.h>
#include <cuda_fp16.h>

#define N_BATCH 4
#define NHEADS  16
#define SEQL    2048
#define HD      64
#define NH      (N_BATCH*NHEADS)   // 64
#define ROWS_ALL (NH*SEQL)         // 131072
#define EMB     1024

// -------- scratch (static device globals; no allocations allowed) --------
__device__ __align__(256) __half  g_q[ROWS_ALL*HD];
__device__ __align__(256) __half  g_k[ROWS_ALL*HD];
__device__ __align__(256) __half  g_v[ROWS_ALL*HD];
__device__ __align__(256) __half  g_att[ROWS_ALL*HD];
__device__ __align__(256) __half  g_wo[EMB*EMB];
__device__ __align__(256) unsigned g_mp[N_BATCH*SEQL*(SEQL/32)];

// -------- helpers --------
__device__ __forceinline__ unsigned smem_u32(const void* p) {
    return (unsigned)__cvta_generic_to_shared(p);
}
__device__ __forceinline__ void ldsm4(unsigned r[4], unsigned addr) {
    asm volatile("ldmatrix.sync.aligned.m8n8.x4.shared.b16 {%0,%1,%2,%3}, [%4];"
        : "=r"(r[0]), "=r"(r[1]), "=r"(r[2]), "=r"(r[3]) : "r"(addr));
}
__device__ __forceinline__ void ldsm4t(unsigned r[4], unsigned addr) {
    asm volatile("ldmatrix.sync.aligned.m8n8.x4.trans.shared.b16 {%0,%1,%2,%3}, [%4];"
        : "=r"(r[0]), "=r"(r[1]), "=r"(r[2]), "=r"(r[3]) : "r"(addr));
}
__device__ __forceinline__ void mma16816(float c[4], const unsigned a[4],
                                         unsigned b0, unsigned b1) {
    asm volatile(
        "mma.sync.aligned.m16n8k16.row.col.f32.f16.f16.f32 "
        "{%0,%1,%2,%3},{%4,%5,%6,%7},{%8,%9},{%0,%1,%2,%3};"
        : "+f"(c[0]), "+f"(c[1]), "+f"(c[2]), "+f"(c[3])
        : "r"(a[0]), "r"(a[1]), "r"(a[2]), "r"(a[3]), "r"(b0), "r"(b1));
}
__device__ __forceinline__ float ex2f(float x) {
    float y; asm("ex2.approx.ftz.f32 %0, %1;" : "=f"(y) : "f"(x)); return y;
}
__device__ __forceinline__ unsigned packh2(float a, float b) {
    __half2 h = __floats2half2_rn(a, b);
    return *reinterpret_cast<unsigned*>(&h);
}
__device__ __forceinline__ void cpa16(unsigned dst, const void* src) {
    asm volatile("cp.async.cg.shared.global [%0], [%1], 16;" :: "r"(dst), "l"(src));
}
__device__ __forceinline__ void cpa4(unsigned dst, const void* src) {
    asm volatile("cp.async.ca.shared.global [%0], [%1], 4;" :: "r"(dst), "l"(src));
}
#define CPA_COMMIT() asm volatile("cp.async.commit_group;" ::: "memory")
#define CPA_WAIT1()  asm volatile("cp.async.wait_group 1;" ::: "memory")

// -------- kernel 1: bitpack the mask (67MB int32 -> 2MB bits) --------
__global__ void pack_mask_kernel(const int* __restrict__ mask) {
    int lane = threadIdx.x & 31;
    int gw   = (blockIdx.x * blockDim.x + threadIdx.x) >> 5;
    int nw   = (gridDim.x * blockDim.x) >> 5;
    const int NW = N_BATCH * SEQL * (SEQL / 32);
    for (int w = gw; w < NW; w += nw) {
        int v = mask[w * 32 + lane];
        unsigned bits = __ballot_sync(0xffffffffu, v != 0);
        if (lane == 0) g_mp[w] = bits;
    }
}

// -------- kernel 2: Wo fp32 -> fp16 --------
__global__ void cvt_wo_kernel(const float* __restrict__ Wo) {
    int i = blockIdx.x * blockDim.x + threadIdx.x;
    int stride = gridDim.x * blockDim.x;
    for (int j = i; j < EMB * EMB / 4; j += stride) {
        float4 f = *(const float4*)&Wo[j * 4];
        *(__half2*)&g_wo[j * 4]     = __floats2half2_rn(f.x, f.y);
        *(__half2*)&g_wo[j * 4 + 2] = __floats2half2_rn(f.z, f.w);
    }
}

// -------- kernel 3: fused QKV projection  (X[131072,64] @ W^T[64,64]) --------
// q output is pre-scaled by log2(e)/sqrt(1024) so attention S is in log2 units.
__global__ __launch_bounds__(128) void proj_kernel(
    const float* __restrict__ keys, const float* __restrict__ values,
    const float* __restrict__ queries, const float* __restrict__ Wk,
    const float* __restrict__ Wv, const float* __restrict__ Wq)
{
    __shared__ __half Xs[64 * 72];
    __shared__ __half Ws[64 * 72];
    int which = blockIdx.y;
    const float* X = which == 0 ? keys : (which == 1 ? values : queries);
    const float* W = which == 0 ? Wk   : (which == 1 ? Wv     : Wq);
    __half* out    = which == 0 ? g_k  : (which == 1 ? g_v    : g_q);
    float osc      = which == 2 ? 0.0450842200278f : 1.0f;  // log2(e)/sqrt(1024)
    int rowbase = blockIdx.x * 64;
    int tid = threadIdx.x, lane = tid & 31, w = tid >> 5;

    for (int i = tid; i < 1024; i += 128) {
        int r = i >> 4, c4 = (i & 15) * 4;
        float4 f = *(const float4*)&X[(rowbase + r) * 64 + c4];
        *(__half2*)&Xs[r * 72 + c4]     = __floats2half2_rn(f.x, f.y);
        *(__half2*)&Xs[r * 72 + c4 + 2] = __floats2half2_rn(f.z, f.w);
        float4 g = *(const float4*)&W[r * 64 + c4];
        *(__half2*)&Ws[r * 72 + c4]     = __floats2half2_rn(g.x, g.y);
        *(__half2*)&Ws[r * 72 + c4 + 2] = __floats2half2_rn(g.z, g.w);
    }
    __syncthreads();
    int m0 = w * 16;
    float O[8][4];
#pragma unroll
    for (int t = 0; t < 8; t++)
#pragma unroll
        for (int j = 0; j < 4; j++) O[t][j] = 0.f;

#pragma unroll
    for (int kk = 0; kk < 4; kk++) {
        unsigned a[4];
        {
            int row = m0 + (lane & 7) + ((lane >> 3) & 1) * 8;
            int col = kk * 16 + (lane >> 4) * 8;
            ldsm4(a, smem_u32(&Xs[row * 72 + col]));
        }
#pragma unroll
        for (int tp = 0; tp < 4; tp++) {
            unsigned b[4];
            int row = tp * 16 + (lane & 7) + (lane >> 4) * 8;
            int col = kk * 16 + ((lane >> 3) & 1) * 8;
            ldsm4(b, smem_u32(&Ws[row * 72 + col]));
            mma16816(O[2 * tp],     a, b[0], b[1]);
            mma16816(O[2 * tp + 1], a, b[2], b[3]);
        }
    }
    int r0 = lane >> 2, c0l = (lane & 3) * 2;
#pragma unroll
    for (int t = 0; t < 8; t++) {
        int col = t * 8 + c0l;
        *(__half2*)&out[(rowbase + m0 + r0) * 64 + col] =
            __floats2half2_rn(O[t][0] * osc, O[t][1] * osc);
        *(__half2*)&out[(rowbase + m0 + r0 + 8) * 64 + col] =
            __floats2half2_rn(O[t][2] * osc, O[t][3] * osc);
    }
}

// -------- kernel 4: flash attention, BQ=64, cp.async double-buffered --------
__global__ __launch_bounds__(128, 4) void attn_kernel()
{
    __shared__ __half Qs[64 * 72];
    __shared__ __half Ks[2][64 * 72];
    __shared__ __half Vs[2][64 * 72];
    __shared__ unsigned Ms[2][128];

    int qt = blockIdx.x;   // 0..31 query tiles
    int nh = blockIdx.y;   // 0..63 (n*16+h)
    int n  = nh >> 4;
    int tid = threadIdx.x, lane = tid & 31, w = tid >> 5;
    const __half* Qg = g_q + (nh * SEQL + qt * 64) * HD;
    const __half* Kg = g_k + nh * SEQL * HD;
    const __half* Vg = g_v + nh * SEQL * HD;
    const unsigned* Mg = g_mp + (n * SEQL + qt * 64) * (SEQL / 32);

    // Q tile (one-time, regular vectorized loads)
    for (int i = tid; i < 512; i += 128) {
        int r = i >> 3, c8 = (i & 7) * 8;
        *(uint4*)&Qs[r * 72 + c8] = *(const uint4*)&Qg[r * 64 + c8];
    }

    auto prefetch = [&](int kvt, int s) {
        int kv = kvt * 64;
        for (int i = tid; i < 1024; i += 128) {
            int r = (i >> 3) & 63, ch = i & 7;
            const __half* src = (i < 512 ? Kg : Vg) + (kv + r) * 64 + ch * 8;
            __half* dst = (i < 512 ? Ks[s] : Vs[s]) + r * 72 + ch * 8;
            cpa16(smem_u32(dst), src);
        }
        cpa4(smem_u32(&Ms[s][tid]),
             &Mg[(tid >> 1) * (SEQL / 32) + (kv >> 5) + (tid & 1)]);
    };

    prefetch(0, 0);
    CPA_COMMIT();
    __syncthreads();   // Qs visible

    int m0 = w * 16;
    unsigned qa[4][4];
#pragma unroll
    for (int kk = 0; kk < 4; kk++) {
        int row = m0 + (lane & 7) + ((lane >> 3) & 1) * 8;
        int col = kk * 16 + (lane >> 4) * 8;
        ldsm4(qa[kk], smem_u32(&Qs[row * 72 + col]));
    }
    float O[8][4];
#pragma unroll
    for (int t = 0; t < 8; t++)
#pragma unroll
        for (int j = 0; j < 4; j++) O[t][j] = 0.f;
    float mrow0 = -1e30f, mrow1 = -1e30f, lrow0 = 0.f, lrow1 = 0.f;
    int r0 = lane >> 2, c0l = (lane & 3) * 2;

    for (int kvt = 0; kvt < 32; kvt++) {
        int s = kvt & 1;
        if (kvt + 1 < 32) prefetch(kvt + 1, s ^ 1);
        CPA_COMMIT();
        CPA_WAIT1();
        __syncthreads();

        // S = Q K^T   (fp32 accum; q pre-scaled so S is in log2 units)
        float S[8][4];
#pragma unroll
        for (int t = 0; t < 8; t++)
#pragma unroll
            for (int j = 0; j < 4; j++) S[t][j] = 0.f;
#pragma unroll
        for (int kk = 0; kk < 4; kk++) {
#pragma unroll
            for (int tp = 0; tp < 4; tp++) {
                unsigned b[4];
                int row = tp * 16 + (lane & 7) + (lane >> 4) * 8;
                int col = kk * 16 + ((lane >> 3) & 1) * 8;
                ldsm4(b, smem_u32(&Ks[s][row * 72 + col]));
                mma16816(S[2 * tp],     qa[kk], b[0], b[1]);
                mma16816(S[2 * tp + 1], qa[kk], b[2], b[3]);
            }
        }
        // mask, online softmax (base-2)
        float rmax0 = -1e30f, rmax1 = -1e30f;
#pragma unroll
        for (int t = 0; t < 8; t++) {
            int col = t * 8 + c0l;
            unsigned w0 = Ms[s][(m0 + r0) * 2 + (col >> 5)];
            unsigned w1 = Ms[s][(m0 + r0 + 8) * 2 + (col >> 5)];
            S[t][0] = ((w0 >> (col & 31)) & 1)       ? S[t][0] : -1e30f;
            S[t][1] = ((w0 >> ((col + 1) & 31)) & 1) ? S[t][1] : -1e30f;
            S[t][2] = ((w1 >> (col & 31)) & 1)       ? S[t][2] : -1e30f;
            S[t][3] = ((w1 >> ((col + 1) & 31)) & 1) ? S[t][3] : -1e30f;
            rmax0 = fmaxf(rmax0, fmaxf(S[t][0], S[t][1]));
            rmax1 = fmaxf(rmax1, fmaxf(S[t][2], S[t][3]));
        }
        rmax0 = fmaxf(rmax0, __shfl_xor_sync(0xffffffffu, rmax0, 1));
        rmax0 = fmaxf(rmax0, __shfl_xor_sync(0xffffffffu, rmax0, 2));
        rmax1 = fmaxf(rmax1, __shfl_xor_sync(0xffffffffu, rmax1, 1));
        rmax1 = fmaxf(rmax1, __shfl_xor_sync(0xffffffffu, rmax1, 2));
        float mn0 = fmaxf(mrow0, rmax0), mn1 = fmaxf(mrow1, rmax1);
        float a0 = ex2f(mrow0 - mn0), a1 = ex2f(mrow1 - mn1);
        mrow0 = mn0; mrow1 = mn1;

        unsigned P[8][2];
        float rs0 = 0.f, rs1 = 0.f;
#pragma unroll
        for (int t = 0; t < 8; t++) {
            float p0 = ex2f(S[t][0] - mn0), p1 = ex2f(S[t][1] - mn0);
            float p2 = ex2f(S[t][2] - mn1), p3 = ex2f(S[t][3] - mn1);
            rs0 += p0 + p1; rs1 += p2 + p3;
            P[t][0] = packh2(p0, p1);
            P[t][1] = packh2(p2, p3);
            O[t][0] *= a0; O[t][1] *= a0; O[t][2] *= a1; O[t][3] *= a1;
        }
        rs0 += __shfl_xor_sync(0xffffffffu, rs0, 1);
        rs0 += __shfl_xor_sync(0xffffffffu, rs0, 2);
        rs1 += __shfl_xor_sync(0xffffffffu, rs1, 1);
        rs1 += __shfl_xor_sync(0xffffffffu, rs1, 2);
        lrow0 = lrow0 * a0 + rs0;
        lrow1 = lrow1 * a1 + rs1;

        // O += P @ V  (V via ldmatrix.trans)
#pragma unroll
        for (int kk = 0; kk < 4; kk++) {
            unsigned pa[4] = {P[2 * kk][0], P[2 * kk][1],
                              P[2 * kk + 1][0], P[2 * kk + 1][1]};
#pragma unroll
            for (int tp = 0; tp < 4; tp++) {
                unsigned b[4];
                int row = kk * 16 + (lane & 7) + ((lane >> 3) & 1) * 8;
                int col = tp * 16 + (lane >> 4) * 8;
                ldsm4t(b, smem_u32(&Vs[s][row * 72 + col]));
                mma16816(O[2 * tp],     pa, b[0], b[1]);
                mma16816(O[2 * tp + 1], pa, b[2], b[3]);
            }
        }
        __syncthreads();
    }
    float inv0 = 1.f / lrow0, inv1 = 1.f / lrow1;
    __half* outp = g_att + (nh * SEQL + qt * 64) * HD;
#pragma unroll
    for (int t = 0; t < 8; t++) {
        int col = t * 8 + c0l;
        *(__half2*)&outp[(m0 + r0) * 64 + col] =
            __floats2half2_rn(O[t][0] * inv0, O[t][1] * inv0);
        *(__half2*)&outp[(m0 + r0 + 8) * 64 + col] =
            __floats2half2_rn(O[t][2] * inv1, O[t][3] * inv1);
    }
}

// -------- kernel 5: output projection  out = X[8192,1024] @ Wo^T + bo --------
__global__ __launch_bounds__(128, 4) void outproj_kernel(
    float* __restrict__ out, const float* __restrict__ bo)
{
    __shared__ __half Xs[2][64 * 72];
    __shared__ __half Ws[2][64 * 72];
    __shared__ float  Bs[64];
    int mt = blockIdx.x, nt = blockIdx.y;
    int tid = threadIdx.x, lane = tid & 31, w = tid >> 5;
    if (tid < 64) Bs[tid] = bo[nt * 64 + tid];

    auto prefetch = [&](int ks, int s) {
        for (int i = tid; i < 1024; i += 128) {
            int r = (i >> 3) & 63, ch = i & 7;
            const __half* src = (i < 512)
                ? &g_att[(mt * 64 + r) * 1024 + ks * 64 + ch * 8]
                : &g_wo[(nt * 64 + r) * 1024 + ks * 64 + ch * 8];
            __half* dst = (i < 512 ? Xs[s] : Ws[s]) + r * 72 + ch * 8;
            cpa16(smem_u32(dst), src);
        }
    };

    prefetch(0, 0);
    CPA_COMMIT();

    float O[8][4];
#pragma unroll
    for (int t = 0; t < 8; t++)
#pragma unroll
        for (int j = 0; j < 4; j++) O[t][j] = 0.f;

    int m0 = w * 16;
    for (int ks = 0; ks < 16; ks++) {
        int s = ks & 1;
        if (ks + 1 < 16) prefetch(ks + 1, s ^ 1);
        CPA_COMMIT();
        CPA_WAIT1();
        __syncthreads();
#pragma unroll
        for (int kk = 0; kk < 4; kk++) {
            unsigned a[4];
            {
                int row = m0 + (lane & 7) + ((lane >> 3) & 1) * 8;
                int col = kk * 16 + (lane >> 4) * 8;
                ldsm4(a, smem_u32(&Xs[s][row * 72 + col]));
            }
#pragma unroll
            for (int tp = 0; tp < 4; tp++) {
                unsigned b[4];
                int row = tp * 16 + (lane & 7) + (lane >> 4) * 8;
                int col = kk * 16 + ((lane >> 3) & 1) * 8;
                ldsm4(b, smem_u32(&Ws[s][row * 72 + col]));
                mma16816(O[2 * tp],     a, b[0], b[1]);
                mma16816(O[2 * tp + 1], a, b[2], b[3]);
            }
        }
        __syncthreads();
    }
    int r0 = lane >> 2, c0l = (lane & 3) * 2;
#pragma unroll
    for (int t = 0; t < 8; t++) {
        int col = t * 8 + c0l;
        float2 v0 = make_float2(O[t][0] + Bs[col], O[t][1] + Bs[col + 1]);
        float2 v1 = make_float2(O[t][2] + Bs[col], O[t][3] + Bs[col + 1]);
        *(float2*)&out[(mt * 64 + m0 + r0) * 1024 + nt * 64 + col] = v0;
        *(float2*)&out[(mt * 64 + m0 + r0 + 8) * 1024 + nt * 64 + col] = v1;
    }
}

// -------- launch --------
extern "C" void kernel_launch(void* const* d_in, const int* in_sizes, int n_in,
                              void* d_out, int out_size)
{
    const float* keys    = (const float*)d_in[0];
    const float* values  = (const float*)d_in[1];
    const float* queries = (const float*)d_in[2];
    const int*   mask    = (const int*)d_in[3];
    const float* Wk      = (const float*)d_in[4];
    const float* Wv      = (const float*)d_in[5];
    const float* Wq      = (const float*)d_in[6];
    const float* Wo      = (const float*)d_in[7];
    const float* bo      = (const float*)d_in[8];
    float* out = (float*)d_out;

    pack_mask_kernel<<<512, 256>>>(mask);
    cvt_wo_kernel<<<256, 256>>>(Wo);
    proj_kernel<<<dim3(ROWS_ALL / 64, 3), 128>>>(keys, values, queries, Wk, Wv, Wq);
    attn_kernel<<<dim3(SEQL / 64, NH), 128>>>();
    outproj_kernel<<<dim3(ROWS_ALL * HD / EMB / 64, EMB / 64), 128>>>(out, bo);
}